// round 13
// baseline (speedup 1.0000x reference)
#include <cuda_runtime.h>
#include <cuda_fp16.h>
#include <cstdint>
#include <cstddef>

// ---------------------------------------------------------------------------
// HolleyGAT: hetero 2-layer GATConv + projections.
// All per-relation work is BATCHED via blockIdx.y descriptors: one launch per
// pipeline stage (GEMMs / CSR build steps / logits / aggregation / epilogues).
// GEMMs on tensor cores (mma.sync tf32, fp32 acc), BM=64. Relation GEMM
// outputs in per-relation fp16 slices. Aggregation: warp/dst-row over CSR,
// single fused pass, one red.v4 per row. Softmax max-free; al = x@(W@a).
// ---------------------------------------------------------------------------

#define CDIV(a,b) (((a)+(b)-1)/(b))

static const int MAX_NU  = 200000;
static const int MAX_NPR = 100000;
static const int MAX_NV  = 20000;
static const int MAX_HROWS = 740000;   // sum of src rows across layer-1 rels

__device__ float g_xp [MAX_NPR*128];
__device__ float g_ou [(size_t)MAX_NU*128];
__device__ float g_op [MAX_NPR*128];
__device__ float g_ov [MAX_NV*128];
__device__ float g_xu2[(size_t)MAX_NU*128];
__device__ float g_xp2[MAX_NPR*128];
__device__ float g_hs [(size_t)MAX_NU*128];     // fp32 scratch (projections)
__device__ float g_hd [(size_t)MAX_NU*128];
__device__ __half g_hsh[(size_t)MAX_HROWS*128]; // per-rel fp16 h slices
__device__ float g_albuf[(size_t)14*MAX_NU*4];
__device__ float g_vmat[12*2*512];
__device__ int g_cnt[800000];
__device__ int g_rowptr[800000];
__device__ int g_cursor[800000];
__device__ int g_part[800000];
__device__ int g_bsum[7*256];
__device__ int g_srt[3600000];

__device__ __forceinline__ uint32_t f2tf32(float x) {
    uint32_t r;
    asm("cvt.rna.tf32.f32 %0, %1;" : "=r"(r) : "f"(x));
    return r;
}

// ---------------------------------------------------------------------------
__global__ void k_feat(const int* __restrict__ pt_id,
                       const float* __restrict__ x_num,
                       const float* __restrict__ pt_emb,
                       const float* __restrict__ fW,
                       const float* __restrict__ fb,
                       const float* __restrict__ pemb,
                       float* __restrict__ xp, int npr)
{
    int idx = blockIdx.x * blockDim.x + threadIdx.x;
    if (idx >= npr * 128) return;
    int row = idx >> 7, c = idx & 127;
    int t = pt_id[row];
    float acc = fb[c];
    const float* pe = pt_emb + (size_t)t * 32;
    #pragma unroll
    for (int k = 0; k < 32; k++) acc += pe[k] * fW[k*128 + c];
    const float* xn = x_num + (size_t)row * 3;
    #pragma unroll
    for (int k = 0; k < 3; k++) acc += xn[k] * fW[(32+k)*128 + c];
    acc = fmaxf(acc, 0.f);
    xp[idx] = pemb[idx] + acc;
}

// ---------------------------------------------------------------------------
// Batched tf32 GEMM: blockIdx.y = relation. BM=64, 256 thr, 8 warps.
// ---------------------------------------------------------------------------
#define WS_STRIDE 136
#define XS_STRIDE 132
static const size_t GEMM_SMEM = (size_t)(128*WS_STRIDE + 64*XS_STRIDE) * 4;

struct GB {
    const float* X[8]; const float* W[8]; const float* bias[8];
    void* H[8]; int n[8]; int relu[8]; int half_[8];
};

__global__ void __launch_bounds__(256)
k_gemm_b(GB B)
{
    int rel = blockIdx.y;
    int n = B.n[rel];
    int row0 = blockIdx.x * 64;
    if (row0 >= n) return;
    const float* X = B.X[rel];
    const float* W = B.W[rel];
    const float* bias = B.bias[rel];
    int do_relu = B.relu[rel], out_half = B.half_[rel];

    extern __shared__ float sm[];
    float* Ws = sm;
    float* Xs = sm + 128*WS_STRIDE;
    int tid = threadIdx.x;

    #pragma unroll 4
    for (int it = 0; it < 16; it++) {
        int idx = it*256 + tid;
        int k = idx >> 5, c4 = (idx & 31) << 2;
        float4 v = *(const float4*)(W + k*128 + c4);
        float4 t;
        t.x = __uint_as_float(f2tf32(v.x));
        t.y = __uint_as_float(f2tf32(v.y));
        t.z = __uint_as_float(f2tf32(v.z));
        t.w = __uint_as_float(f2tf32(v.w));
        *(float4*)(Ws + k*WS_STRIDE + c4) = t;
    }
    #pragma unroll 4
    for (int it = 0; it < 8; it++) {
        int idx = it*256 + tid;
        int r = idx >> 5, c4 = (idx & 31) << 2;
        float4 v = (row0 + r < n) ? *(const float4*)(X + (size_t)(row0+r)*128 + c4)
                                  : make_float4(0.f,0.f,0.f,0.f);
        float4 t;
        t.x = __uint_as_float(f2tf32(v.x));
        t.y = __uint_as_float(f2tf32(v.y));
        t.z = __uint_as_float(f2tf32(v.z));
        t.w = __uint_as_float(f2tf32(v.w));
        *(float4*)(Xs + r*XS_STRIDE + c4) = t;
    }
    __syncthreads();

    int w = tid >> 5, lane = tid & 31;
    int wr = w >> 1, wc = w & 1;
    int g = lane >> 2, q = lane & 3;

    float acc[8][4];
    #pragma unroll
    for (int nt = 0; nt < 8; nt++)
        #pragma unroll
        for (int j = 0; j < 4; j++) acc[nt][j] = 0.f;

    #pragma unroll 4
    for (int kt = 0; kt < 16; kt++) {
        int kb = kt * 8;
        uint32_t a[4];
        {
            const float* p = Xs + (wr*16 + g)*XS_STRIDE + kb + q;
            a[0] = __float_as_uint(p[0]);
            a[1] = __float_as_uint(p[8*XS_STRIDE]);
            a[2] = __float_as_uint(p[4]);
            a[3] = __float_as_uint(p[8*XS_STRIDE + 4]);
        }
        #pragma unroll
        for (int nt = 0; nt < 8; nt++) {
            const float* p = Ws + (kb + q)*WS_STRIDE + wc*64 + nt*8 + g;
            uint32_t b0 = __float_as_uint(p[0]);
            uint32_t b1 = __float_as_uint(p[4*WS_STRIDE]);
            asm volatile(
                "mma.sync.aligned.m16n8k8.row.col.f32.tf32.tf32.f32 "
                "{%0,%1,%2,%3}, {%4,%5,%6,%7}, {%8,%9}, {%0,%1,%2,%3};"
                : "+f"(acc[nt][0]), "+f"(acc[nt][1]),
                  "+f"(acc[nt][2]), "+f"(acc[nt][3])
                : "r"(a[0]), "r"(a[1]), "r"(a[2]), "r"(a[3]),
                  "r"(b0), "r"(b1));
        }
    }

    int r0 = row0 + wr*16 + g;
    #pragma unroll
    for (int nt = 0; nt < 8; nt++) {
        int c = wc*64 + nt*8 + q*2;
        float2 v0 = make_float2(acc[nt][0], acc[nt][1]);
        float2 v1 = make_float2(acc[nt][2], acc[nt][3]);
        if (bias) {
            float b0 = bias[c], b1 = bias[c+1];
            v0.x += b0; v0.y += b1; v1.x += b0; v1.y += b1;
        }
        if (do_relu) {
            v0.x = fmaxf(v0.x,0.f); v0.y = fmaxf(v0.y,0.f);
            v1.x = fmaxf(v1.x,0.f); v1.y = fmaxf(v1.y,0.f);
        }
        if (out_half) {
            __half* H = (__half*)B.H[rel];
            if (r0 < n)     *(__half2*)(H + (size_t)r0*128 + c)     = __floats2half2_rn(v0.x, v0.y);
            if (r0 + 8 < n) *(__half2*)(H + (size_t)(r0+8)*128 + c) = __floats2half2_rn(v1.x, v1.y);
        } else {
            float* H = (float*)B.H[rel];
            if (r0 < n)     *(float2*)(H + (size_t)r0*128 + c)     = v0;
            if (r0 + 8 < n) *(float2*)(H + (size_t)(r0+8)*128 + c) = v1;
        }
    }
}

// ---------------------------------------------------------------------------
__global__ void k_wa_all(const float* __restrict__ c1W,
                         const float* __restrict__ c1as,
                         const float* __restrict__ c1ad,
                         const float* __restrict__ c2W,
                         const float* __restrict__ c2as,
                         const float* __restrict__ c2ad,
                         float* __restrict__ vmat)
{
    const int l2map[5] = {0,1,3,5,6};
    int b = blockIdx.x;
    int rel  = (b < 7) ? b : l2map[b-7];
    const float* W   = ((b < 7) ? c1W  : c2W ) + (size_t)rel*16384;
    const float* as_ = ((b < 7) ? c1as : c2as) + rel*128;
    const float* ad_ = ((b < 7) ? c1ad : c2ad) + rel*128;
    float* vs = vmat + (size_t)b*1024;
    float* vd = vs + 512;

    int k = threadIdx.x;
    #pragma unroll
    for (int h = 0; h < 4; h++) {
        float accs = 0.f, accd = 0.f;
        const float* Wr = W + (size_t)k*128 + h*32;
        const float* asr = as_ + h*32;
        const float* adr = ad_ + h*32;
        #pragma unroll
        for (int c = 0; c < 32; c++) {
            float wv = Wr[c];
            accs += wv * asr[c];
            accd += wv * adr[c];
        }
        vs[k*4 + h] = accs;
        vd[k*4 + h] = accd;
    }
}

// ---------------------------------------------------------------------------
// Batched multi-vector logits: blockIdx.y = node type (up to 3).
// ---------------------------------------------------------------------------
struct AlxB {
    const float* X[3]; int n[3]; int nv[3];
    const float* v[3][6]; float* out[3][6];
};

__global__ void k_alx_b(AlxB A)
{
    int ty = blockIdx.y;
    int n = A.n[ty];
    int g = blockIdx.x * blockDim.x + threadIdx.x;
    int row = g >> 5, lane = g & 31;
    if (row >= n) return;
    const float* X = A.X[ty];
    float4 x = *(const float4*)(X + (size_t)row*128 + lane*4);
    int nv = A.nv[ty];
    for (int j = 0; j < nv; j++) {
        const float4* v4 = (const float4*)A.v[ty][j];
        float4 v0 = __ldg(v4 + lane*4 + 0);
        float4 v1 = __ldg(v4 + lane*4 + 1);
        float4 v2 = __ldg(v4 + lane*4 + 2);
        float4 v3 = __ldg(v4 + lane*4 + 3);
        float4 p;
        p.x = x.x*v0.x + x.y*v1.x + x.z*v2.x + x.w*v3.x;
        p.y = x.x*v0.y + x.y*v1.y + x.z*v2.y + x.w*v3.y;
        p.z = x.x*v0.z + x.y*v1.z + x.z*v2.z + x.w*v3.z;
        p.w = x.x*v0.w + x.y*v1.w + x.z*v2.w + x.w*v3.w;
        #pragma unroll
        for (int off = 16; off >= 1; off >>= 1) {
            p.x += __shfl_xor_sync(0xffffffffu, p.x, off);
            p.y += __shfl_xor_sync(0xffffffffu, p.y, off);
            p.z += __shfl_xor_sync(0xffffffffu, p.z, off);
            p.w += __shfl_xor_sync(0xffffffffu, p.w, off);
        }
        if (lane == 0) *(float4*)(A.out[ty][j] + (size_t)row*4) = p;
    }
}

// ---------------------------------------------------------------------------
// Batched bias init: blockIdx.y = node type.
// ---------------------------------------------------------------------------
struct InitB {
    float* out[3]; int n[3];
    const float* b0[3]; const float* b1[3]; const float* b2[3];
};

__global__ void k_init_b(InitB B)
{
    int ty = blockIdx.y;
    int i = blockIdx.x * blockDim.x + threadIdx.x;
    if (i >= B.n[ty] * 128) return;
    int c = i & 127;
    float v = B.b0[ty][c] + B.b1[ty][c];
    if (B.b2[ty]) v += B.b2[ty][c];
    B.out[ty][i] = v;
}

// ---------------------------------------------------------------------------
// Batched CSR build: blockIdx.y = direction (7).
// ---------------------------------------------------------------------------
struct EdgeB {
    const int* src[7]; const int* dst[7];
    int* cnt[7]; int* cursor[7]; int* srt[7];
    const int* part[7]; int* rowptr[7]; int* bsum[7];
    int E[7]; int nd[7];
};

__global__ void k_hist_b(EdgeB B)
{
    int d = blockIdx.y;
    int i = blockIdx.x*blockDim.x + threadIdx.x;
    if (i < B.E[d]) atomicAdd(B.cnt[d] + B.dst[d][i], 1);
}

__global__ void k_scan_part_b(EdgeB B, int* __restrict__ partout_unused)
{
    int d = blockIdx.y;
    int n = B.nd[d];
    __shared__ int smv[1024];
    int i = blockIdx.x*1024 + threadIdx.x;
    int x = (i < n) ? B.cnt[d][i] : 0;
    smv[threadIdx.x] = x; __syncthreads();
    #pragma unroll
    for (int off = 1; off < 1024; off <<= 1) {
        int v = (threadIdx.x >= off) ? smv[threadIdx.x - off] : 0;
        __syncthreads();
        smv[threadIdx.x] += v;
        __syncthreads();
    }
    if (i < n) ((int*)B.part[d])[i] = smv[threadIdx.x] - x;
    if (threadIdx.x == 1023 && blockIdx.x < 256) B.bsum[d][blockIdx.x] = smv[1023];
}

__global__ void k_scan_top_b(EdgeB B)
{
    int d = blockIdx.y;
    int nb = CDIV(B.nd[d], 1024);
    __shared__ int smv[1024];
    int x = ((int)threadIdx.x < nb) ? B.bsum[d][threadIdx.x] : 0;
    smv[threadIdx.x] = x; __syncthreads();
    #pragma unroll
    for (int off = 1; off < 1024; off <<= 1) {
        int v = (threadIdx.x >= off) ? smv[threadIdx.x - off] : 0;
        __syncthreads();
        smv[threadIdx.x] += v;
        __syncthreads();
    }
    if ((int)threadIdx.x < nb) B.bsum[d][threadIdx.x] = smv[threadIdx.x] - x;
}

__global__ void k_scan_add_b(EdgeB B)
{
    int d = blockIdx.y;
    int n = B.nd[d];
    int i = blockIdx.x*1024 + threadIdx.x;
    if (i < n) {
        int v = B.part[d][i] + B.bsum[d][blockIdx.x];
        B.rowptr[d][i] = v;
        B.cursor[d][i] = v;
    }
}

__global__ void k_scatter_b(EdgeB B)
{
    int d = blockIdx.y;
    int i = blockIdx.x*blockDim.x + threadIdx.x;
    if (i < B.E[d]) {
        int p = atomicAdd(B.cursor[d] + B.dst[d][i], 1);
        B.srt[d][p] = B.src[d][i];
    }
}

// ---------------------------------------------------------------------------
// Batched CSR GAT aggregation: blockIdx.y = relation. Warp per dst row,
// fused den+acc pass, one red.v4 per row.
// ---------------------------------------------------------------------------
struct GatB {
    const int* rowptr[8]; const int* cnt[8]; const int* srt[8];
    const float* alS[8]; const float* alD[8];
    const __half* Hs[8]; float* out[8]; int nd[8];
};

__global__ void k_gat_b(GatB B)
{
    int rel = blockIdx.y;
    int nd = B.nd[rel];
    int g = blockIdx.x*blockDim.x + threadIdx.x;
    int row = g >> 5, lane = g & 31;
    if (row >= nd) return;
    int m = __ldg(B.cnt[rel] + row);
    if (m == 0) return;
    int start = __ldg(B.rowptr[rel] + row);
    int h = lane >> 3;
    float adh = __ldg(B.alD[rel] + (size_t)row*4 + h);
    const int* srt = B.srt[rel];
    const float* alS = B.alS[rel];
    const __half* Hs = B.Hs[rel];

    float den = 0.f;
    float4 acc = make_float4(0.f,0.f,0.f,0.f);
    for (int i = 0; i < m; i++) {
        int s = __ldg(srt + start + i);
        float e = __ldg(alS + (size_t)s*4 + h) + adh;
        if (e < 0.f) e *= 0.2f;
        float ex = __expf(e);
        den += ex;
        const __half2* hp = (const __half2*)(Hs + (size_t)s*128) + lane*2;
        float2 f01 = __half22float2(hp[0]);
        float2 f23 = __half22float2(hp[1]);
        acc.x += ex*f01.x; acc.y += ex*f01.y;
        acc.z += ex*f23.x; acc.w += ex*f23.y;
    }
    float inv = 1.f/(den + 1e-16f);
    float* o = B.out[rel] + (size_t)row*128 + lane*4;
    asm volatile("red.global.add.v4.f32 [%0], {%1, %2, %3, %4};"
                 :: "l"(__cvta_generic_to_global(o)),
                    "f"(acc.x*inv), "f"(acc.y*inv),
                    "f"(acc.z*inv), "f"(acc.w*inv)
                 : "memory");
}

// ---------------------------------------------------------------------------
struct EluB { float* p[3]; int cnt[3]; };
__global__ void k_elu_b(EluB B)
{
    int ty = blockIdx.y;
    int i = blockIdx.x * blockDim.x + threadIdx.x;
    if (i >= B.cnt[ty]) return;
    float v = B.p[ty][i];
    B.p[ty][i] = (v > 0.f) ? v : (__expf(v) - 1.f);
}

struct NormB { const float* H[2]; float* out[2]; int n[2]; };
__global__ void k_norm_b(NormB B)
{
    int ty = blockIdx.y;
    int g = blockIdx.x * blockDim.x + threadIdx.x;
    int row = g >> 5, lane = g & 31;
    if (row >= B.n[ty]) return;
    float4 v = *(const float4*)(B.H[ty] + (size_t)row*128 + lane*4);
    float ss = v.x*v.x + v.y*v.y + v.z*v.z + v.w*v.w;
    #pragma unroll
    for (int off = 16; off >= 1; off >>= 1)
        ss += __shfl_xor_sync(0xffffffffu, ss, off);
    float s = 1.f / fmaxf(sqrtf(ss), 1e-12f);
    v.x *= s; v.y *= s; v.z *= s; v.w *= s;
    *(float4*)(B.out[ty] + (size_t)row*128 + lane*4) = v;
}

// ---------------------------------------------------------------------------
// host orchestration
// ---------------------------------------------------------------------------
extern "C" void kernel_launch(void* const* d_in, const int* in_sizes, int n_in,
                              void* d_out, int out_size)
{
    const int*   pt_id   = (const int*)  d_in[0];
    const float* x_num   = (const float*)d_in[1];
    const int*   e_up    = (const int*)  d_in[2];
    const int*   e_pv    = (const int*)  d_in[3];
    const int*   e_uv    = (const int*)  d_in[4];
    const int*   e_pp    = (const int*)  d_in[5];
    const float* user_e  = (const float*)d_in[6];
    const float* prod_e  = (const float*)d_in[7];
    const float* veh_e   = (const float*)d_in[8];
    const float* pt_emb  = (const float*)d_in[9];
    const float* fmlp_W  = (const float*)d_in[10];
    const float* fmlp_b  = (const float*)d_in[11];
    const float* c1W     = (const float*)d_in[12];
    const float* c1as    = (const float*)d_in[13];
    const float* c1ad    = (const float*)d_in[14];
    const float* c1b     = (const float*)d_in[15];
    const float* c2W     = (const float*)d_in[16];
    const float* c2as    = (const float*)d_in[17];
    const float* c2ad    = (const float*)d_in[18];
    const float* c2b     = (const float*)d_in[19];
    const float* upW1    = (const float*)d_in[20];
    const float* upb1    = (const float*)d_in[21];
    const float* upW2    = (const float*)d_in[22];
    const float* upb2    = (const float*)d_in[23];
    const float* ppW1    = (const float*)d_in[24];
    const float* ppb1    = (const float*)d_in[25];
    const float* ppW2    = (const float*)d_in[26];
    const float* ppb2    = (const float*)d_in[27];

    const int NPR = in_sizes[0];
    const int NU  = in_sizes[6] / 128;
    const int NV  = in_sizes[8] / 128;
    const int EUP = in_sizes[2] / 2;
    const int EPV = in_sizes[3] / 2;
    const int EUV = in_sizes[4] / 2;
    const int EPP = in_sizes[5] / 2;

    float *Sxp, *Sou, *Sop, *Sov, *Sxu2, *Sxp2, *Shs, *Shd, *Salbuf, *Svmat;
    __half* Shsh;
    int *Scnt, *Srowptr, *Scursor, *Spart, *Sbsum, *Ssrt;
    cudaGetSymbolAddress((void**)&Sxp , g_xp);
    cudaGetSymbolAddress((void**)&Sou , g_ou);
    cudaGetSymbolAddress((void**)&Sop , g_op);
    cudaGetSymbolAddress((void**)&Sov , g_ov);
    cudaGetSymbolAddress((void**)&Sxu2, g_xu2);
    cudaGetSymbolAddress((void**)&Sxp2, g_xp2);
    cudaGetSymbolAddress((void**)&Shs , g_hs);
    cudaGetSymbolAddress((void**)&Shd , g_hd);
    cudaGetSymbolAddress((void**)&Shsh, g_hsh);
    cudaGetSymbolAddress((void**)&Salbuf, g_albuf);
    cudaGetSymbolAddress((void**)&Svmat, g_vmat);
    cudaGetSymbolAddress((void**)&Scnt, g_cnt);
    cudaGetSymbolAddress((void**)&Srowptr, g_rowptr);
    cudaGetSymbolAddress((void**)&Scursor, g_cursor);
    cudaGetSymbolAddress((void**)&Spart, g_part);
    cudaGetSymbolAddress((void**)&Sbsum, g_bsum);
    cudaGetSymbolAddress((void**)&Ssrt, g_srt);

    cudaFuncSetAttribute(k_gemm_b, cudaFuncAttributeMaxDynamicSharedMemorySize,
                         (int)GEMM_SMEM);

    auto alslot = [&](int slot) -> float* {
        return Salbuf + (size_t)slot * MAX_NU * 4;
    };

    const int *up0 = e_up, *up1 = e_up + EUP;
    const int *pv0 = e_pv, *pv1 = e_pv + EPV;
    const int *uv0 = e_uv, *uv1 = e_uv + EUV;
    const int *pp0 = e_pp, *pp1 = e_pp + EPP;

    const int* dsrc[7] = {up0, up1, pv0, pv1, uv0, uv1, pp0};
    const int* ddst[7] = {up1, up0, pv1, pv0, uv1, uv0, pp1};
    int  dE [7] = {EUP, EUP, EPV, EPV, EUV, EUV, EPP};
    int  dND[7] = {NPR, NU,  NV,  NPR, NV,  NU,  NPR};
    int  cbase[7], ebase[7];
    int totN = 0, maxE = 0, maxND = 0;
    {
        int cb = 0, eb = 0;
        for (int d = 0; d < 7; d++) {
            cbase[d] = cb; ebase[d] = eb;
            cb += dND[d]; eb += dE[d];
            if (dE[d] > maxE) maxE = dE[d];
            if (dND[d] > maxND) maxND = dND[d];
        }
        totN = cb;
    }

    // ---------------- launch 0: W@a precompute -----------------------------
    k_wa_all<<<12,128>>>(c1W, c1as, c1ad, c2W, c2as, c2ad, Svmat);
    // ---------------- launch 1: product features ---------------------------
    k_feat<<<CDIV(NPR*128,256),256>>>(pt_id, x_num, pt_emb, fmlp_W, fmlp_b,
                                      prod_e, Sxp, NPR);
    // ---------------- launch 2: layer-1 bias init (3 types) ----------------
    {
        InitB B{};
        B.out[0]=Sou;  B.n[0]=NU;  B.b0[0]=c1b+1*128; B.b1[0]=c1b+5*128; B.b2[0]=nullptr;
        B.out[1]=Sop;  B.n[1]=NPR; B.b0[1]=c1b+0*128; B.b1[1]=c1b+3*128; B.b2[1]=c1b+6*128;
        B.out[2]=Sov;  B.n[2]=NV;  B.b0[2]=c1b+2*128; B.b1[2]=c1b+4*128; B.b2[2]=nullptr;
        k_init_b<<<dim3(CDIV(NU*128,256),3),256>>>(B);
    }

    // L1 relation h slices
    const float* l1x[7]; int l1n[7]; size_t l1off[7];
    {
        const float* xs[7] = {user_e, Sxp, Sxp, veh_e, user_e, veh_e, Sxp};
        int ns[7] = {NU, NPR, NPR, NV, NU, NV, NPR};
        size_t off = 0;
        for (int r = 0; r < 7; r++) { l1x[r]=xs[r]; l1n[r]=ns[r]; l1off[r]=off; off+=ns[r]; }
    }

    // ---------------- launch 3: batched layer-1 GEMMs (profiled) -----------
    {
        GB B{};
        for (int r = 0; r < 7; r++) {
            B.X[r]=l1x[r]; B.W[r]=c1W + (size_t)r*16384; B.bias[r]=nullptr;
            B.H[r]=Shsh + l1off[r]*128; B.n[r]=l1n[r]; B.relu[r]=0; B.half_[r]=1;
        }
        k_gemm_b<<<dim3(CDIV(NU,64),7),256,GEMM_SMEM>>>(B);
    }

    // ---------------- CSR build (5 launches + memset) ----------------------
    EdgeB EB{};
    for (int d = 0; d < 7; d++) {
        EB.src[d]=dsrc[d]; EB.dst[d]=ddst[d];
        EB.cnt[d]=Scnt+cbase[d]; EB.cursor[d]=Scursor+cbase[d];
        EB.srt[d]=Ssrt+ebase[d]; EB.part[d]=Spart+cbase[d];
        EB.rowptr[d]=Srowptr+cbase[d]; EB.bsum[d]=Sbsum+d*256;
        EB.E[d]=dE[d]; EB.nd[d]=dND[d];
    }
    cudaMemsetAsync(Scnt, 0, (size_t)totN*sizeof(int));
    k_hist_b<<<dim3(CDIV(maxE,256),7),256>>>(EB);
    k_scan_part_b<<<dim3(CDIV(maxND,1024),7),1024>>>(EB, nullptr);
    k_scan_top_b<<<dim3(1,7),1024>>>(EB);
    k_scan_add_b<<<dim3(CDIV(maxND,1024),7),1024>>>(EB);
    k_scatter_b<<<dim3(CDIV(maxE,256),7),256>>>(EB);

    // ---------------- layer-1 logits (1 launch) ----------------------------
    {
        AlxB A{};
        const int uvm[4]={0,4,1,5}, urole[4]={0,0,1,1}, uslot[4]={0,1,2,3};
        const int pvm[6]={1,2,6,0,3,6}, prole[6]={0,0,0,1,1,1}, pslot[6]={4,5,6,7,8,9};
        const int vvm[4]={3,5,2,4}, vrole[4]={0,0,1,1}, vslot[4]={10,11,12,13};
        A.X[0]=user_e; A.n[0]=NU;  A.nv[0]=4;
        A.X[1]=Sxp;    A.n[1]=NPR; A.nv[1]=6;
        A.X[2]=veh_e;  A.n[2]=NV;  A.nv[2]=4;
        for (int j=0;j<4;j++){A.v[0][j]=Svmat+(size_t)uvm[j]*1024+urole[j]*512; A.out[0][j]=alslot(uslot[j]);}
        for (int j=0;j<6;j++){A.v[1][j]=Svmat+(size_t)pvm[j]*1024+prole[j]*512; A.out[1][j]=alslot(pslot[j]);}
        for (int j=0;j<4;j++){A.v[2][j]=Svmat+(size_t)vvm[j]*1024+vrole[j]*512; A.out[2][j]=alslot(vslot[j]);}
        k_alx_b<<<dim3(CDIV(NU*32,256),3),256>>>(A);
    }

    // ---------------- layer-1 aggregation (1 launch) -----------------------
    {
        GatB B{};
        // rel -> (dir, alS slot, alD slot, out)
        int   sS[7] = {0, 4, 5, 10, 1, 11, 6};
        int   sD[7] = {7, 2, 12, 8, 13, 3, 9};
        float* outp[7] = {Sop, Sou, Sov, Sop, Sov, Sou, Sop};
        for (int r = 0; r < 7; r++) {
            B.rowptr[r]=EB.rowptr[r]; B.cnt[r]=EB.cnt[r]; B.srt[r]=EB.srt[r];
            B.alS[r]=alslot(sS[r]); B.alD[r]=alslot(sD[r]);
            B.Hs[r]=Shsh + l1off[r]*128; B.out[r]=outp[r]; B.nd[r]=dND[r];
        }
        k_gat_b<<<dim3(CDIV(NU*32,256),7),256>>>(B);
    }
    // ---------------- layer-1 elu (1 launch) -------------------------------
    {
        EluB B{};
        B.p[0]=Sou; B.cnt[0]=NU*128;
        B.p[1]=Sop; B.cnt[1]=NPR*128;
        B.p[2]=Sov; B.cnt[2]=NV*128;
        k_elu_b<<<dim3(CDIV(NU*128,256),3),256>>>(B);
    }

    // ---------------- layer-2 ----------------------------------------------
    {
        InitB B{};
        B.out[0]=Sxu2; B.n[0]=NU;  B.b0[0]=c2b+1*128; B.b1[0]=c2b+5*128; B.b2[0]=nullptr;
        B.out[1]=Sxp2; B.n[1]=NPR; B.b0[1]=c2b+0*128; B.b1[1]=c2b+3*128; B.b2[1]=c2b+6*128;
        B.out[2]=Sxu2; B.n[2]=0;   B.b0[2]=c2b;       B.b1[2]=c2b;       B.b2[2]=nullptr;
        k_init_b<<<dim3(CDIV(NU*128,256),3),256>>>(B);
    }
    // L2 rels (pruned): {0,1,3,5,6} with src {ou,op,ov,ov,op}, dirs {0,1,3,5,6}
    int l2rel[5] = {0,1,3,5,6};
    const float* l2x[5] = {Sou, Sop, Sov, Sov, Sop};
    int l2n[5]; size_t l2off[5];
    {
        int ns[5] = {NU, NPR, NV, NV, NPR};
        size_t off = 0;
        for (int r = 0; r < 5; r++) { l2n[r]=ns[r]; l2off[r]=off; off+=ns[r]; }
    }
    {
        GB B{};
        for (int r = 0; r < 5; r++) {
            B.X[r]=l2x[r]; B.W[r]=c2W + (size_t)l2rel[r]*16384; B.bias[r]=nullptr;
            B.H[r]=Shsh + l2off[r]*128; B.n[r]=l2n[r]; B.relu[r]=0; B.half_[r]=1;
        }
        k_gemm_b<<<dim3(CDIV(NU,64),5),256,GEMM_SMEM>>>(B);
    }
    {
        AlxB A{};
        const int uvm[3]={7,8,10}, urole[3]={0,1,1}, uslot[3]={0,1,2};
        const int pvm[5]={8,11,7,9,11}, prole[5]={0,0,1,1,1}, pslot[5]={4,5,6,7,8};
        const int vvm[2]={9,10}, vrole[2]={0,0}, vslot[2]={10,11};
        A.X[0]=Sou; A.n[0]=NU;  A.nv[0]=3;
        A.X[1]=Sop; A.n[1]=NPR; A.nv[1]=5;
        A.X[2]=Sov; A.n[2]=NV;  A.nv[2]=2;
        for (int j=0;j<3;j++){A.v[0][j]=Svmat+(size_t)uvm[j]*1024+urole[j]*512; A.out[0][j]=alslot(uslot[j]);}
        for (int j=0;j<5;j++){A.v[1][j]=Svmat+(size_t)pvm[j]*1024+prole[j]*512; A.out[1][j]=alslot(pslot[j]);}
        for (int j=0;j<2;j++){A.v[2][j]=Svmat+(size_t)vvm[j]*1024+vrole[j]*512; A.out[2][j]=alslot(vslot[j]);}
        k_alx_b<<<dim3(CDIV(NU*32,256),3),256>>>(A);
    }
    {
        GatB B{};
        // L2 rel r uses dir l2rel[r]; alS/alD slots per R11 mapping
        int   sS[5] = {0, 4, 10, 11, 5};
        int   sD[5] = {6, 1, 7, 2, 8};
        float* outp[5] = {Sxp2, Sxu2, Sxp2, Sxu2, Sxp2};
        for (int r = 0; r < 5; r++) {
            int d = l2rel[r];
            B.rowptr[r]=EB.rowptr[d]; B.cnt[r]=EB.cnt[d]; B.srt[r]=EB.srt[d];
            B.alS[r]=alslot(sS[r]); B.alD[r]=alslot(sD[r]);
            B.Hs[r]=Shsh + l2off[r]*128; B.out[r]=outp[r]; B.nd[r]=dND[d];
        }
        k_gat_b<<<dim3(CDIV(NU*32,256),5),256>>>(B);
    }
    {
        EluB B{};
        B.p[0]=Sxu2; B.cnt[0]=NU*128;
        B.p[1]=Sxp2; B.cnt[1]=NPR*128;
        B.p[2]=Sxu2; B.cnt[2]=0;
        k_elu_b<<<dim3(CDIV(NU*128,256),3),256>>>(B);
    }

    // ---------------- projections + norm (3 launches) ----------------------
    float* out = (float*)d_out;
    {
        GB B{};
        B.X[0]=Sxu2; B.W[0]=upW1; B.bias[0]=upb1; B.H[0]=Shs; B.n[0]=NU;  B.relu[0]=1; B.half_[0]=0;
        B.X[1]=Sxp2; B.W[1]=ppW1; B.bias[1]=ppb1; B.H[1]=Shd; B.n[1]=NPR; B.relu[1]=1; B.half_[1]=0;
        k_gemm_b<<<dim3(CDIV(NU,64),2),256,GEMM_SMEM>>>(B);
    }
    {
        GB B{};
        B.X[0]=Shs; B.W[0]=upW2; B.bias[0]=upb2; B.H[0]=Sou; B.n[0]=NU;  B.relu[0]=0; B.half_[0]=0;
        B.X[1]=Shd; B.W[1]=ppW2; B.bias[1]=ppb2; B.H[1]=Sop; B.n[1]=NPR; B.relu[1]=0; B.half_[1]=0;
        k_gemm_b<<<dim3(CDIV(NU,64),2),256,GEMM_SMEM>>>(B);
    }
    {
        NormB B{};
        B.H[0]=Sou; B.out[0]=out;                     B.n[0]=NU;
        B.H[1]=Sop; B.out[1]=out + (size_t)NU*128;    B.n[1]=NPR;
        k_norm_b<<<dim3(CDIV(NU*32,256),2),256>>>(B);
    }
}

// round 15
// speedup vs baseline: 1.0034x; 1.0034x over previous
#include <cuda_runtime.h>
#include <cuda_fp16.h>
#include <cstdint>
#include <cstddef>

// ---------------------------------------------------------------------------
// HolleyGAT: hetero 2-layer GATConv + projections.
// GEMMs / CSR build / logits / epilogues BATCHED via blockIdx.y.
// Edge aggregation runs SERIALLY per relation (preserves L2 locality of the
// per-relation h slice + dst accumulation; batching it thrashed L2 in R13).
// GEMMs: mma.sync tf32 fp32-acc, BM=64. h stored fp16 per-relation.
// Aggregation: warp/dst-row over CSR, fused den+acc, one red.v4 per row.
// Softmax max-free; al = x @ (W@a) linearity.
// ---------------------------------------------------------------------------

#define CDIV(a,b) (((a)+(b)-1)/(b))

static const int MAX_NU  = 200000;
static const int MAX_NPR = 100000;
static const int MAX_NV  = 20000;
static const int MAX_HROWS = 740000;

__device__ float g_xp [MAX_NPR*128];
__device__ float g_ou [(size_t)MAX_NU*128];
__device__ float g_op [MAX_NPR*128];
__device__ float g_ov [MAX_NV*128];
__device__ float g_xu2[(size_t)MAX_NU*128];
__device__ float g_xp2[MAX_NPR*128];
__device__ float g_hs [(size_t)MAX_NU*128];
__device__ float g_hd [(size_t)MAX_NU*128];
__device__ __half g_hsh[(size_t)MAX_HROWS*128];
__device__ float g_albuf[(size_t)14*MAX_NU*4];
__device__ float g_vmat[12*2*512];
__device__ int g_cnt[800000];
__device__ int g_rowptr[800000];
__device__ int g_cursor[800000];
__device__ int g_part[800000];
__device__ int g_bsum[7*256];
__device__ int g_srt[3600000];

__device__ __forceinline__ uint32_t f2tf32(float x) {
    uint32_t r;
    asm("cvt.rna.tf32.f32 %0, %1;" : "=r"(r) : "f"(x));
    return r;
}

// ---------------------------------------------------------------------------
__global__ void k_feat(const int* __restrict__ pt_id,
                       const float* __restrict__ x_num,
                       const float* __restrict__ pt_emb,
                       const float* __restrict__ fW,
                       const float* __restrict__ fb,
                       const float* __restrict__ pemb,
                       float* __restrict__ xp, int npr)
{
    int idx = blockIdx.x * blockDim.x + threadIdx.x;
    if (idx >= npr * 128) return;
    int row = idx >> 7, c = idx & 127;
    int t = pt_id[row];
    float acc = fb[c];
    const float* pe = pt_emb + (size_t)t * 32;
    #pragma unroll
    for (int k = 0; k < 32; k++) acc += pe[k] * fW[k*128 + c];
    const float* xn = x_num + (size_t)row * 3;
    #pragma unroll
    for (int k = 0; k < 3; k++) acc += xn[k] * fW[(32+k)*128 + c];
    acc = fmaxf(acc, 0.f);
    xp[idx] = pemb[idx] + acc;
}

// ---------------------------------------------------------------------------
// Batched tf32 GEMM: blockIdx.y = relation. BM=64, 256 thr, 8 warps.
// ---------------------------------------------------------------------------
#define WS_STRIDE 136
#define XS_STRIDE 132
static const size_t GEMM_SMEM = (size_t)(128*WS_STRIDE + 64*XS_STRIDE) * 4;

struct GB {
    const float* X[8]; const float* W[8]; const float* bias[8];
    void* H[8]; int n[8]; int relu[8]; int half_[8];
};

__global__ void __launch_bounds__(256)
k_gemm_b(GB B)
{
    int rel = blockIdx.y;
    int n = B.n[rel];
    int row0 = blockIdx.x * 64;
    if (row0 >= n) return;
    const float* X = B.X[rel];
    const float* W = B.W[rel];
    const float* bias = B.bias[rel];
    int do_relu = B.relu[rel], out_half = B.half_[rel];

    extern __shared__ float sm[];
    float* Ws = sm;
    float* Xs = sm + 128*WS_STRIDE;
    int tid = threadIdx.x;

    #pragma unroll 4
    for (int it = 0; it < 16; it++) {
        int idx = it*256 + tid;
        int k = idx >> 5, c4 = (idx & 31) << 2;
        float4 v = *(const float4*)(W + k*128 + c4);
        float4 t;
        t.x = __uint_as_float(f2tf32(v.x));
        t.y = __uint_as_float(f2tf32(v.y));
        t.z = __uint_as_float(f2tf32(v.z));
        t.w = __uint_as_float(f2tf32(v.w));
        *(float4*)(Ws + k*WS_STRIDE + c4) = t;
    }
    #pragma unroll 4
    for (int it = 0; it < 8; it++) {
        int idx = it*256 + tid;
        int r = idx >> 5, c4 = (idx & 31) << 2;
        float4 v = (row0 + r < n) ? *(const float4*)(X + (size_t)(row0+r)*128 + c4)
                                  : make_float4(0.f,0.f,0.f,0.f);
        float4 t;
        t.x = __uint_as_float(f2tf32(v.x));
        t.y = __uint_as_float(f2tf32(v.y));
        t.z = __uint_as_float(f2tf32(v.z));
        t.w = __uint_as_float(f2tf32(v.w));
        *(float4*)(Xs + r*XS_STRIDE + c4) = t;
    }
    __syncthreads();

    int w = tid >> 5, lane = tid & 31;
    int wr = w >> 1, wc = w & 1;
    int g = lane >> 2, q = lane & 3;

    float acc[8][4];
    #pragma unroll
    for (int nt = 0; nt < 8; nt++)
        #pragma unroll
        for (int j = 0; j < 4; j++) acc[nt][j] = 0.f;

    #pragma unroll 4
    for (int kt = 0; kt < 16; kt++) {
        int kb = kt * 8;
        uint32_t a[4];
        {
            const float* p = Xs + (wr*16 + g)*XS_STRIDE + kb + q;
            a[0] = __float_as_uint(p[0]);
            a[1] = __float_as_uint(p[8*XS_STRIDE]);
            a[2] = __float_as_uint(p[4]);
            a[3] = __float_as_uint(p[8*XS_STRIDE + 4]);
        }
        #pragma unroll
        for (int nt = 0; nt < 8; nt++) {
            const float* p = Ws + (kb + q)*WS_STRIDE + wc*64 + nt*8 + g;
            uint32_t b0 = __float_as_uint(p[0]);
            uint32_t b1 = __float_as_uint(p[4*WS_STRIDE]);
            asm volatile(
                "mma.sync.aligned.m16n8k8.row.col.f32.tf32.tf32.f32 "
                "{%0,%1,%2,%3}, {%4,%5,%6,%7}, {%8,%9}, {%0,%1,%2,%3};"
                : "+f"(acc[nt][0]), "+f"(acc[nt][1]),
                  "+f"(acc[nt][2]), "+f"(acc[nt][3])
                : "r"(a[0]), "r"(a[1]), "r"(a[2]), "r"(a[3]),
                  "r"(b0), "r"(b1));
        }
    }

    int r0 = row0 + wr*16 + g;
    #pragma unroll
    for (int nt = 0; nt < 8; nt++) {
        int c = wc*64 + nt*8 + q*2;
        float2 v0 = make_float2(acc[nt][0], acc[nt][1]);
        float2 v1 = make_float2(acc[nt][2], acc[nt][3]);
        if (bias) {
            float b0 = bias[c], b1 = bias[c+1];
            v0.x += b0; v0.y += b1; v1.x += b0; v1.y += b1;
        }
        if (do_relu) {
            v0.x = fmaxf(v0.x,0.f); v0.y = fmaxf(v0.y,0.f);
            v1.x = fmaxf(v1.x,0.f); v1.y = fmaxf(v1.y,0.f);
        }
        if (out_half) {
            __half* H = (__half*)B.H[rel];
            if (r0 < n)     *(__half2*)(H + (size_t)r0*128 + c)     = __floats2half2_rn(v0.x, v0.y);
            if (r0 + 8 < n) *(__half2*)(H + (size_t)(r0+8)*128 + c) = __floats2half2_rn(v1.x, v1.y);
        } else {
            float* H = (float*)B.H[rel];
            if (r0 < n)     *(float2*)(H + (size_t)r0*128 + c)     = v0;
            if (r0 + 8 < n) *(float2*)(H + (size_t)(r0+8)*128 + c) = v1;
        }
    }
}

// ---------------------------------------------------------------------------
__global__ void k_wa_all(const float* __restrict__ c1W,
                         const float* __restrict__ c1as,
                         const float* __restrict__ c1ad,
                         const float* __restrict__ c2W,
                         const float* __restrict__ c2as,
                         const float* __restrict__ c2ad,
                         float* __restrict__ vmat)
{
    const int l2map[5] = {0,1,3,5,6};
    int b = blockIdx.x;
    int rel  = (b < 7) ? b : l2map[b-7];
    const float* W   = ((b < 7) ? c1W  : c2W ) + (size_t)rel*16384;
    const float* as_ = ((b < 7) ? c1as : c2as) + rel*128;
    const float* ad_ = ((b < 7) ? c1ad : c2ad) + rel*128;
    float* vs = vmat + (size_t)b*1024;
    float* vd = vs + 512;

    int k = threadIdx.x;
    #pragma unroll
    for (int h = 0; h < 4; h++) {
        float accs = 0.f, accd = 0.f;
        const float* Wr = W + (size_t)k*128 + h*32;
        const float* asr = as_ + h*32;
        const float* adr = ad_ + h*32;
        #pragma unroll
        for (int c = 0; c < 32; c++) {
            float wv = Wr[c];
            accs += wv * asr[c];
            accd += wv * adr[c];
        }
        vs[k*4 + h] = accs;
        vd[k*4 + h] = accd;
    }
}

// ---------------------------------------------------------------------------
// Batched multi-vector logits: blockIdx.y = node type (up to 3).
// ---------------------------------------------------------------------------
struct AlxB {
    const float* X[3]; int n[3]; int nv[3];
    const float* v[3][6]; float* out[3][6];
};

__global__ void k_alx_b(AlxB A)
{
    int ty = blockIdx.y;
    int n = A.n[ty];
    int g = blockIdx.x * blockDim.x + threadIdx.x;
    int row = g >> 5, lane = g & 31;
    if (row >= n) return;
    const float* X = A.X[ty];
    float4 x = *(const float4*)(X + (size_t)row*128 + lane*4);
    int nv = A.nv[ty];
    for (int j = 0; j < nv; j++) {
        const float4* v4 = (const float4*)A.v[ty][j];
        float4 v0 = __ldg(v4 + lane*4 + 0);
        float4 v1 = __ldg(v4 + lane*4 + 1);
        float4 v2 = __ldg(v4 + lane*4 + 2);
        float4 v3 = __ldg(v4 + lane*4 + 3);
        float4 p;
        p.x = x.x*v0.x + x.y*v1.x + x.z*v2.x + x.w*v3.x;
        p.y = x.x*v0.y + x.y*v1.y + x.z*v2.y + x.w*v3.y;
        p.z = x.x*v0.z + x.y*v1.z + x.z*v2.z + x.w*v3.z;
        p.w = x.x*v0.w + x.y*v1.w + x.z*v2.w + x.w*v3.w;
        #pragma unroll
        for (int off = 16; off >= 1; off >>= 1) {
            p.x += __shfl_xor_sync(0xffffffffu, p.x, off);
            p.y += __shfl_xor_sync(0xffffffffu, p.y, off);
            p.z += __shfl_xor_sync(0xffffffffu, p.z, off);
            p.w += __shfl_xor_sync(0xffffffffu, p.w, off);
        }
        if (lane == 0) *(float4*)(A.out[ty][j] + (size_t)row*4) = p;
    }
}

// ---------------------------------------------------------------------------
struct InitB {
    float* out[3]; int n[3];
    const float* b0[3]; const float* b1[3]; const float* b2[3];
};

__global__ void k_init_b(InitB B)
{
    int ty = blockIdx.y;
    int i = blockIdx.x * blockDim.x + threadIdx.x;
    if (i >= B.n[ty] * 128) return;
    int c = i & 127;
    float v = B.b0[ty][c] + B.b1[ty][c];
    if (B.b2[ty]) v += B.b2[ty][c];
    B.out[ty][i] = v;
}

// ---------------------------------------------------------------------------
// Batched CSR build: blockIdx.y = direction (7).
// ---------------------------------------------------------------------------
struct EdgeB {
    const int* src[7]; const int* dst[7];
    int* cnt[7]; int* cursor[7]; int* srt[7];
    const int* part[7]; int* rowptr[7]; int* bsum[7];
    int E[7]; int nd[7];
};

__global__ void k_hist_b(EdgeB B)
{
    int d = blockIdx.y;
    int i = blockIdx.x*blockDim.x + threadIdx.x;
    if (i < B.E[d]) atomicAdd(B.cnt[d] + B.dst[d][i], 1);
}

__global__ void k_scan_part_b(EdgeB B)
{
    int d = blockIdx.y;
    int n = B.nd[d];
    __shared__ int smv[1024];
    int i = blockIdx.x*1024 + threadIdx.x;
    int x = (i < n) ? B.cnt[d][i] : 0;
    smv[threadIdx.x] = x; __syncthreads();
    #pragma unroll
    for (int off = 1; off < 1024; off <<= 1) {
        int v = (threadIdx.x >= off) ? smv[threadIdx.x - off] : 0;
        __syncthreads();
        smv[threadIdx.x] += v;
        __syncthreads();
    }
    if (i < n) ((int*)B.part[d])[i] = smv[threadIdx.x] - x;
    if (threadIdx.x == 1023 && blockIdx.x < 256) B.bsum[d][blockIdx.x] = smv[1023];
}

__global__ void k_scan_top_b(EdgeB B)
{
    int d = blockIdx.y;
    int nb = CDIV(B.nd[d], 1024);
    __shared__ int smv[1024];
    int x = ((int)threadIdx.x < nb) ? B.bsum[d][threadIdx.x] : 0;
    smv[threadIdx.x] = x; __syncthreads();
    #pragma unroll
    for (int off = 1; off < 1024; off <<= 1) {
        int v = (threadIdx.x >= off) ? smv[threadIdx.x - off] : 0;
        __syncthreads();
        smv[threadIdx.x] += v;
        __syncthreads();
    }
    if ((int)threadIdx.x < nb) B.bsum[d][threadIdx.x] = smv[threadIdx.x] - x;
}

__global__ void k_scan_add_b(EdgeB B)
{
    int d = blockIdx.y;
    int n = B.nd[d];
    int i = blockIdx.x*1024 + threadIdx.x;
    if (i < n) {
        int v = B.part[d][i] + B.bsum[d][blockIdx.x];
        B.rowptr[d][i] = v;
        B.cursor[d][i] = v;
    }
}

__global__ void k_scatter_b(EdgeB B)
{
    int d = blockIdx.y;
    int i = blockIdx.x*blockDim.x + threadIdx.x;
    if (i < B.E[d]) {
        int p = atomicAdd(B.cursor[d] + B.dst[d][i], 1);
        B.srt[d][p] = B.src[d][i];
    }
}

// ---------------------------------------------------------------------------
// SERIAL per-relation CSR GAT aggregation: warp per dst row, fused den+acc,
// one red.v4 per row. (Serial launches preserve L2 locality per relation.)
// ---------------------------------------------------------------------------
__global__ void k_gat_one(const int* __restrict__ rowptr, const int* __restrict__ cnt,
                          const int* __restrict__ srt,
                          const float* __restrict__ alS, const float* __restrict__ alD,
                          const __half* __restrict__ Hs, float* __restrict__ out, int nd)
{
    int g = blockIdx.x*blockDim.x + threadIdx.x;
    int row = g >> 5, lane = g & 31;
    if (row >= nd) return;
    int m = __ldg(cnt + row);
    if (m == 0) return;
    int start = __ldg(rowptr + row);
    int h = lane >> 3;
    float adh = __ldg(alD + (size_t)row*4 + h);

    float den = 0.f;
    float4 acc = make_float4(0.f,0.f,0.f,0.f);
    for (int i = 0; i < m; i++) {
        int s = __ldg(srt + start + i);
        float e = __ldg(alS + (size_t)s*4 + h) + adh;
        if (e < 0.f) e *= 0.2f;
        float ex = __expf(e);
        den += ex;
        const __half2* hp = (const __half2*)(Hs + (size_t)s*128) + lane*2;
        float2 f01 = __half22float2(hp[0]);
        float2 f23 = __half22float2(hp[1]);
        acc.x += ex*f01.x; acc.y += ex*f01.y;
        acc.z += ex*f23.x; acc.w += ex*f23.y;
    }
    float inv = 1.f/(den + 1e-16f);
    float* o = out + (size_t)row*128 + lane*4;
    asm volatile("red.global.add.v4.f32 [%0], {%1, %2, %3, %4};"
                 :: "l"(__cvta_generic_to_global(o)),
                    "f"(acc.x*inv), "f"(acc.y*inv),
                    "f"(acc.z*inv), "f"(acc.w*inv)
                 : "memory");
}

// ---------------------------------------------------------------------------
struct EluB { float* p[3]; int cnt[3]; };
__global__ void k_elu_b(EluB B)
{
    int ty = blockIdx.y;
    int i = blockIdx.x * blockDim.x + threadIdx.x;
    if (i >= B.cnt[ty]) return;
    float v = B.p[ty][i];
    B.p[ty][i] = (v > 0.f) ? v : (__expf(v) - 1.f);
}

struct NormB { const float* H[2]; float* out[2]; int n[2]; };
__global__ void k_norm_b(NormB B)
{
    int ty = blockIdx.y;
    int g = blockIdx.x * blockDim.x + threadIdx.x;
    int row = g >> 5, lane = g & 31;
    if (row >= B.n[ty]) return;
    float4 v = *(const float4*)(B.H[ty] + (size_t)row*128 + lane*4);
    float ss = v.x*v.x + v.y*v.y + v.z*v.z + v.w*v.w;
    #pragma unroll
    for (int off = 16; off >= 1; off >>= 1)
        ss += __shfl_xor_sync(0xffffffffu, ss, off);
    float s = 1.f / fmaxf(sqrtf(ss), 1e-12f);
    v.x *= s; v.y *= s; v.z *= s; v.w *= s;
    *(float4*)(B.out[ty] + (size_t)row*128 + lane*4) = v;
}

// ---------------------------------------------------------------------------
// host orchestration
// ---------------------------------------------------------------------------
extern "C" void kernel_launch(void* const* d_in, const int* in_sizes, int n_in,
                              void* d_out, int out_size)
{
    const int*   pt_id   = (const int*)  d_in[0];
    const float* x_num   = (const float*)d_in[1];
    const int*   e_up    = (const int*)  d_in[2];
    const int*   e_pv    = (const int*)  d_in[3];
    const int*   e_uv    = (const int*)  d_in[4];
    const int*   e_pp    = (const int*)  d_in[5];
    const float* user_e  = (const float*)d_in[6];
    const float* prod_e  = (const float*)d_in[7];
    const float* veh_e   = (const float*)d_in[8];
    const float* pt_emb  = (const float*)d_in[9];
    const float* fmlp_W  = (const float*)d_in[10];
    const float* fmlp_b  = (const float*)d_in[11];
    const float* c1W     = (const float*)d_in[12];
    const float* c1as    = (const float*)d_in[13];
    const float* c1ad    = (const float*)d_in[14];
    const float* c1b     = (const float*)d_in[15];
    const float* c2W     = (const float*)d_in[16];
    const float* c2as    = (const float*)d_in[17];
    const float* c2ad    = (const float*)d_in[18];
    const float* c2b     = (const float*)d_in[19];
    const float* upW1    = (const float*)d_in[20];
    const float* upb1    = (const float*)d_in[21];
    const float* upW2    = (const float*)d_in[22];
    const float* upb2    = (const float*)d_in[23];
    const float* ppW1    = (const float*)d_in[24];
    const float* ppb1    = (const float*)d_in[25];
    const float* ppW2    = (const float*)d_in[26];
    const float* ppb2    = (const float*)d_in[27];

    const int NPR = in_sizes[0];
    const int NU  = in_sizes[6] / 128;
    const int NV  = in_sizes[8] / 128;
    const int EUP = in_sizes[2] / 2;
    const int EPV = in_sizes[3] / 2;
    const int EUV = in_sizes[4] / 2;
    const int EPP = in_sizes[5] / 2;

    float *Sxp, *Sou, *Sop, *Sov, *Sxu2, *Sxp2, *Shs, *Shd, *Salbuf, *Svmat;
    __half* Shsh;
    int *Scnt, *Srowptr, *Scursor, *Spart, *Sbsum, *Ssrt;
    cudaGetSymbolAddress((void**)&Sxp , g_xp);
    cudaGetSymbolAddress((void**)&Sou , g_ou);
    cudaGetSymbolAddress((void**)&Sop , g_op);
    cudaGetSymbolAddress((void**)&Sov , g_ov);
    cudaGetSymbolAddress((void**)&Sxu2, g_xu2);
    cudaGetSymbolAddress((void**)&Sxp2, g_xp2);
    cudaGetSymbolAddress((void**)&Shs , g_hs);
    cudaGetSymbolAddress((void**)&Shd , g_hd);
    cudaGetSymbolAddress((void**)&Shsh, g_hsh);
    cudaGetSymbolAddress((void**)&Salbuf, g_albuf);
    cudaGetSymbolAddress((void**)&Svmat, g_vmat);
    cudaGetSymbolAddress((void**)&Scnt, g_cnt);
    cudaGetSymbolAddress((void**)&Srowptr, g_rowptr);
    cudaGetSymbolAddress((void**)&Scursor, g_cursor);
    cudaGetSymbolAddress((void**)&Spart, g_part);
    cudaGetSymbolAddress((void**)&Sbsum, g_bsum);
    cudaGetSymbolAddress((void**)&Ssrt, g_srt);

    cudaFuncSetAttribute(k_gemm_b, cudaFuncAttributeMaxDynamicSharedMemorySize,
                         (int)GEMM_SMEM);

    auto alslot = [&](int slot) -> float* {
        return Salbuf + (size_t)slot * MAX_NU * 4;
    };

    const int *up0 = e_up, *up1 = e_up + EUP;
    const int *pv0 = e_pv, *pv1 = e_pv + EPV;
    const int *uv0 = e_uv, *uv1 = e_uv + EUV;
    const int *pp0 = e_pp, *pp1 = e_pp + EPP;

    const int* dsrc[7] = {up0, up1, pv0, pv1, uv0, uv1, pp0};
    const int* ddst[7] = {up1, up0, pv1, pv0, uv1, uv0, pp1};
    int  dE [7] = {EUP, EUP, EPV, EPV, EUV, EUV, EPP};
    int  dND[7] = {NPR, NU,  NV,  NPR, NV,  NU,  NPR};
    int  cbase[7], ebase[7];
    int totN = 0, maxE = 0, maxND = 0;
    {
        int cb = 0, eb = 0;
        for (int d = 0; d < 7; d++) {
            cbase[d] = cb; ebase[d] = eb;
            cb += dND[d]; eb += dE[d];
            if (dE[d] > maxE) maxE = dE[d];
            if (dND[d] > maxND) maxND = dND[d];
        }
        totN = cb;
    }

    // ---------------- W@a precompute + features + init ---------------------
    k_wa_all<<<12,128>>>(c1W, c1as, c1ad, c2W, c2as, c2ad, Svmat);
    k_feat<<<CDIV(NPR*128,256),256>>>(pt_id, x_num, pt_emb, fmlp_W, fmlp_b,
                                      prod_e, Sxp, NPR);
    {
        InitB B{};
        B.out[0]=Sou;  B.n[0]=NU;  B.b0[0]=c1b+1*128; B.b1[0]=c1b+5*128; B.b2[0]=nullptr;
        B.out[1]=Sop;  B.n[1]=NPR; B.b0[1]=c1b+0*128; B.b1[1]=c1b+3*128; B.b2[1]=c1b+6*128;
        B.out[2]=Sov;  B.n[2]=NV;  B.b0[2]=c1b+2*128; B.b1[2]=c1b+4*128; B.b2[2]=nullptr;
        k_init_b<<<dim3(CDIV(NU*128,256),3),256>>>(B);
    }

    // L1 relation h slices
    const float* l1x[7]; int l1n[7]; size_t l1off[7];
    {
        const float* xs[7] = {user_e, Sxp, Sxp, veh_e, user_e, veh_e, Sxp};
        int ns[7] = {NU, NPR, NPR, NV, NU, NV, NPR};
        size_t off = 0;
        for (int r = 0; r < 7; r++) { l1x[r]=xs[r]; l1n[r]=ns[r]; l1off[r]=off; off+=ns[r]; }
    }

    // ---------------- batched layer-1 GEMMs (launch #3, profiled) ----------
    {
        GB B{};
        for (int r = 0; r < 7; r++) {
            B.X[r]=l1x[r]; B.W[r]=c1W + (size_t)r*16384; B.bias[r]=nullptr;
            B.H[r]=Shsh + l1off[r]*128; B.n[r]=l1n[r]; B.relu[r]=0; B.half_[r]=1;
        }
        k_gemm_b<<<dim3(CDIV(NU,64),7),256,GEMM_SMEM>>>(B);
    }

    // ---------------- batched CSR build -------------------------------------
    EdgeB EB{};
    for (int d = 0; d < 7; d++) {
        EB.src[d]=dsrc[d]; EB.dst[d]=ddst[d];
        EB.cnt[d]=Scnt+cbase[d]; EB.cursor[d]=Scursor+cbase[d];
        EB.srt[d]=Ssrt+ebase[d]; EB.part[d]=Spart+cbase[d];
        EB.rowptr[d]=Srowptr+cbase[d]; EB.bsum[d]=Sbsum+d*256;
        EB.E[d]=dE[d]; EB.nd[d]=dND[d];
    }
    cudaMemsetAsync(Scnt, 0, (size_t)totN*sizeof(int));
    k_hist_b<<<dim3(CDIV(maxE,256),7),256>>>(EB);
    k_scan_part_b<<<dim3(CDIV(maxND,1024),7),1024>>>(EB);
    k_scan_top_b<<<dim3(1,7),1024>>>(EB);
    k_scan_add_b<<<dim3(CDIV(maxND,1024),7),1024>>>(EB);
    k_scatter_b<<<dim3(CDIV(maxE,256),7),256>>>(EB);

    // ---------------- layer-1 logits (1 launch) ----------------------------
    {
        AlxB A{};
        const int uvm[4]={0,4,1,5}, urole[4]={0,0,1,1}, uslot[4]={0,1,2,3};
        const int pvm[6]={1,2,6,0,3,6}, prole[6]={0,0,0,1,1,1}, pslot[6]={4,5,6,7,8,9};
        const int vvm[4]={3,5,2,4}, vrole[4]={0,0,1,1}, vslot[4]={10,11,12,13};
        A.X[0]=user_e; A.n[0]=NU;  A.nv[0]=4;
        A.X[1]=Sxp;    A.n[1]=NPR; A.nv[1]=6;
        A.X[2]=veh_e;  A.n[2]=NV;  A.nv[2]=4;
        for (int j=0;j<4;j++){A.v[0][j]=Svmat+(size_t)uvm[j]*1024+urole[j]*512; A.out[0][j]=alslot(uslot[j]);}
        for (int j=0;j<6;j++){A.v[1][j]=Svmat+(size_t)pvm[j]*1024+prole[j]*512; A.out[1][j]=alslot(pslot[j]);}
        for (int j=0;j<4;j++){A.v[2][j]=Svmat+(size_t)vvm[j]*1024+vrole[j]*512; A.out[2][j]=alslot(vslot[j]);}
        k_alx_b<<<dim3(CDIV(NU*32,256),3),256>>>(A);
    }

    // ---------------- layer-1 aggregation: SERIAL per relation -------------
    {
        int   sS[7] = {0, 4, 5, 10, 1, 11, 6};
        int   sD[7] = {7, 2, 12, 8, 13, 3, 9};
        float* outp[7] = {Sop, Sou, Sov, Sop, Sov, Sou, Sop};
        for (int r = 0; r < 7; r++) {
            k_gat_one<<<CDIV(dND[r]*32,256),256>>>(
                Srowptr+cbase[r], Scnt+cbase[r], Ssrt+ebase[r],
                alslot(sS[r]), alslot(sD[r]),
                Shsh + l1off[r]*128, outp[r], dND[r]);
        }
    }
    {
        EluB B{};
        B.p[0]=Sou; B.cnt[0]=NU*128;
        B.p[1]=Sop; B.cnt[1]=NPR*128;
        B.p[2]=Sov; B.cnt[2]=NV*128;
        k_elu_b<<<dim3(CDIV(NU*128,256),3),256>>>(B);
    }

    // ---------------- layer-2 ----------------------------------------------
    {
        InitB B{};
        B.out[0]=Sxu2; B.n[0]=NU;  B.b0[0]=c2b+1*128; B.b1[0]=c2b+5*128; B.b2[0]=nullptr;
        B.out[1]=Sxp2; B.n[1]=NPR; B.b0[1]=c2b+0*128; B.b1[1]=c2b+3*128; B.b2[1]=c2b+6*128;
        B.out[2]=Sxu2; B.n[2]=0;   B.b0[2]=c2b;       B.b1[2]=c2b;       B.b2[2]=nullptr;
        k_init_b<<<dim3(CDIV(NU*128,256),3),256>>>(B);
    }
    int l2rel[5] = {0,1,3,5,6};
    const float* l2x[5] = {Sou, Sop, Sov, Sov, Sop};
    int l2n[5]; size_t l2off[5];
    {
        int ns[5] = {NU, NPR, NV, NV, NPR};
        size_t off = 0;
        for (int r = 0; r < 5; r++) { l2n[r]=ns[r]; l2off[r]=off; off+=ns[r]; }
    }
    {
        GB B{};
        for (int r = 0; r < 5; r++) {
            B.X[r]=l2x[r]; B.W[r]=c2W + (size_t)l2rel[r]*16384; B.bias[r]=nullptr;
            B.H[r]=Shsh + l2off[r]*128; B.n[r]=l2n[r]; B.relu[r]=0; B.half_[r]=1;
        }
        k_gemm_b<<<dim3(CDIV(NU,64),5),256,GEMM_SMEM>>>(B);
    }
    {
        AlxB A{};
        const int uvm[3]={7,8,10}, urole[3]={0,1,1}, uslot[3]={0,1,2};
        const int pvm[5]={8,11,7,9,11}, prole[5]={0,0,1,1,1}, pslot[5]={4,5,6,7,8};
        const int vvm[2]={9,10}, vrole[2]={0,0}, vslot[2]={10,11};
        A.X[0]=Sou; A.n[0]=NU;  A.nv[0]=3;
        A.X[1]=Sop; A.n[1]=NPR; A.nv[1]=5;
        A.X[2]=Sov; A.n[2]=NV;  A.nv[2]=2;
        for (int j=0;j<3;j++){A.v[0][j]=Svmat+(size_t)uvm[j]*1024+urole[j]*512; A.out[0][j]=alslot(uslot[j]);}
        for (int j=0;j<5;j++){A.v[1][j]=Svmat+(size_t)pvm[j]*1024+prole[j]*512; A.out[1][j]=alslot(pslot[j]);}
        for (int j=0;j<2;j++){A.v[2][j]=Svmat+(size_t)vvm[j]*1024+vrole[j]*512; A.out[2][j]=alslot(vslot[j]);}
        k_alx_b<<<dim3(CDIV(NU*32,256),3),256>>>(A);
    }
    {
        int   sS[5] = {0, 4, 10, 11, 5};
        int   sD[5] = {6, 1, 7, 2, 8};
        float* outp[5] = {Sxp2, Sxu2, Sxp2, Sxu2, Sxp2};
        for (int r = 0; r < 5; r++) {
            int d = l2rel[r];
            k_gat_one<<<CDIV(dND[d]*32,256),256>>>(
                Srowptr+cbase[d], Scnt+cbase[d], Ssrt+ebase[d],
                alslot(sS[r]), alslot(sD[r]),
                Shsh + l2off[r]*128, outp[r], dND[d]);
        }
    }
    {
        EluB B{};
        B.p[0]=Sxu2; B.cnt[0]=NU*128;
        B.p[1]=Sxp2; B.cnt[1]=NPR*128;
        B.p[2]=Sxu2; B.cnt[2]=0;
        k_elu_b<<<dim3(CDIV(NU*128,256),3),256>>>(B);
    }

    // ---------------- projections + norm -----------------------------------
    float* out = (float*)d_out;
    {
        GB B{};
        B.X[0]=Sxu2; B.W[0]=upW1; B.bias[0]=upb1; B.H[0]=Shs; B.n[0]=NU;  B.relu[0]=1; B.half_[0]=0;
        B.X[1]=Sxp2; B.W[1]=ppW1; B.bias[1]=ppb1; B.H[1]=Shd; B.n[1]=NPR; B.relu[1]=1; B.half_[1]=0;
        k_gemm_b<<<dim3(CDIV(NU,64),2),256,GEMM_SMEM>>>(B);
    }
    {
        GB B{};
        B.X[0]=Shs; B.W[0]=upW2; B.bias[0]=upb2; B.H[0]=Sou; B.n[0]=NU;  B.relu[0]=0; B.half_[0]=0;
        B.X[1]=Shd; B.W[1]=ppW2; B.bias[1]=ppb2; B.H[1]=Sop; B.n[1]=NPR; B.relu[1]=0; B.half_[1]=0;
        k_gemm_b<<<dim3(CDIV(NU,64),2),256,GEMM_SMEM>>>(B);
    }
    {
        NormB B{};
        B.H[0]=Sou; B.out[0]=out;                     B.n[0]=NU;
        B.H[1]=Sop; B.out[1]=out + (size_t)NU*128;    B.n[1]=NPR;
        k_norm_b<<<dim3(CDIV(NU*32,256),2),256>>>(B);
    }
}